// round 4
// baseline (speedup 1.0000x reference)
#include <cuda_runtime.h>
#include <cstdint>

// ---------------------------------------------------------------------------
// ClinicalRLModel: embed-sum -> x@W_ih^T -> GRU(64 steps) -> policy logits at
// obs t=62 (rnn t=63) -> threefry gumbel argmax -> select rnn[53+act] ->
// fused=relu([rnn63,sel]@Wf^T+bf) -> out = fused@Wo^T+bo
// RNG: JAX partitionable threefry, 32-bit bits = out0 ^ out1, counter=(0, i).
// ---------------------------------------------------------------------------

#define B_SZ 128
#define T_SZ 64
#define C_SZ 24
#define EMB 128
#define HID 128
#define G3 384           // 3*HID
#define K2E 256          // 2*EMB

// scratch (device globals: no allocation allowed)
__device__ float g_x[B_SZ * T_SZ * K2E];      // (8192, 256)
__device__ float g_xproj[B_SZ * T_SZ * G3];   // (8192, 384)
__device__ float g_rnn[B_SZ * T_SZ * HID];    // (128, 64, 128)

// ---------------------------------------------------------------------------
// K1: embedding gather + sum over C, writes x = [e1 | e2]
// ---------------------------------------------------------------------------
__global__ void embed_kernel(const int* __restrict__ cond,
                             const int* __restrict__ proc,
                             const float* __restrict__ emb_c,
                             const float* __restrict__ emb_p) {
    int gw   = (blockIdx.x * blockDim.x + threadIdx.x) >> 5;
    int lane = threadIdx.x & 31;
    if (gw >= B_SZ * T_SZ * 2) return;
    int table = gw & 1;
    int bt    = gw >> 1;

    const int*   idx = (table ? proc : cond) + bt * C_SZ;
    const float* tab = table ? emb_p : emb_c;

    float4 acc = make_float4(0.f, 0.f, 0.f, 0.f);
#pragma unroll
    for (int j = 0; j < C_SZ; j++) {
        int r = __ldg(&idx[j]);
        float4 v = __ldg(((const float4*)(tab + (long)r * EMB)) + lane);
        acc.x += v.x; acc.y += v.y; acc.z += v.z; acc.w += v.w;
    }
    ((float4*)(g_x + (long)bt * K2E + table * EMB))[lane] = acc;
}

// ---------------------------------------------------------------------------
// K2: x_proj = x @ W_ih^T + b_ih   (M=8192, N=384, K=256), fp32 SIMT tiled
// ---------------------------------------------------------------------------
#define BM 64
#define BN 64
#define BKK 16
__global__ __launch_bounds__(256) void xproj_gemm(const float* __restrict__ Wih,
                                                  const float* __restrict__ bih) {
    __shared__ float As[BKK][BM + 4];
    __shared__ float Bs[BKK][BN + 4];
    int bm = blockIdx.x * BM;
    int bn = blockIdx.y * BN;
    int tid = threadIdx.x;
    int tx = tid & 15, ty = tid >> 4;

    int lrow = tid >> 2;          // 0..63
    int lcol = (tid & 3) * 4;     // 0,4,8,12

    float acc[4][4] = {};
    for (int k0 = 0; k0 < K2E; k0 += BKK) {
        float4 av = *(const float4*)(g_x + (long)(bm + lrow) * K2E + k0 + lcol);
        float4 bv = *(const float4*)(Wih + (long)(bn + lrow) * K2E + k0 + lcol);
        As[lcol + 0][lrow] = av.x; As[lcol + 1][lrow] = av.y;
        As[lcol + 2][lrow] = av.z; As[lcol + 3][lrow] = av.w;
        Bs[lcol + 0][lrow] = bv.x; Bs[lcol + 1][lrow] = bv.y;
        Bs[lcol + 2][lrow] = bv.z; Bs[lcol + 3][lrow] = bv.w;
        __syncthreads();
#pragma unroll
        for (int kk = 0; kk < BKK; kk++) {
            float a[4], b[4];
#pragma unroll
            for (int i = 0; i < 4; i++) a[i] = As[kk][ty * 4 + i];
#pragma unroll
            for (int i = 0; i < 4; i++) b[i] = Bs[kk][tx * 4 + i];
#pragma unroll
            for (int i = 0; i < 4; i++)
#pragma unroll
                for (int j = 0; j < 4; j++) acc[i][j] += a[i] * b[j];
        }
        __syncthreads();
    }
#pragma unroll
    for (int i = 0; i < 4; i++) {
        int m = bm + ty * 4 + i;
#pragma unroll
        for (int j = 0; j < 4; j++) {
            int n = bn + tx * 4 + j;
            g_xproj[(long)m * G3 + n] = acc[i][j] + bih[n];
        }
    }
}

// ---------------------------------------------------------------------------
// K3: GRU. one block per batch row; 384 threads; W_hh register-resident
// ---------------------------------------------------------------------------
__global__ __launch_bounds__(G3) void gru_kernel(const float* __restrict__ Whh,
                                                 const float* __restrict__ bhh) {
    int b = blockIdx.x;
    int g = threadIdx.x;      // 0..383
    __shared__ float h_sh[HID];
    __shared__ float srz[2 * HID];
    __shared__ float sxn[HID];
    __shared__ float shn[HID];

    float w[HID];
#pragma unroll
    for (int k = 0; k < HID; k += 4) {
        float4 v = *(const float4*)(Whh + (long)g * HID + k);
        w[k] = v.x; w[k + 1] = v.y; w[k + 2] = v.z; w[k + 3] = v.w;
    }
    float bb = bhh[g];
    if (g < HID) h_sh[g] = 0.f;
    __syncthreads();

    const float* xp_base = g_xproj + (long)b * T_SZ * G3;
    float* rnn_base = g_rnn + (long)b * T_SZ * HID;

    for (int t = 0; t < T_SZ; t++) {
        float xp = xp_base[t * G3 + g];
        float acc = bb;
#pragma unroll
        for (int k = 0; k < HID; k++) acc += w[k] * h_sh[k];
        if (g < 2 * HID) {
            srz[g] = xp + acc;
        } else {
            sxn[g - 2 * HID] = xp;
            shn[g - 2 * HID] = acc;
        }
        __syncthreads();
        if (g < HID) {
            float r = 1.f / (1.f + expf(-srz[g]));
            float z = 1.f / (1.f + expf(-srz[HID + g]));
            float n = tanhf(sxn[g] + r * shn[g]);
            float hn = (1.f - z) * n + z * h_sh[g];
            h_sh[g] = hn;
            rnn_base[t * HID + g] = hn;
        }
        __syncthreads();
    }
}

// ---------------------------------------------------------------------------
// threefry2x32, JAX-exact (key injections + rotation schedule)
// ---------------------------------------------------------------------------
__device__ __forceinline__ uint32_t rotl32(uint32_t v, int d) {
    return (v << d) | (v >> (32 - d));
}
__device__ void threefry2x32(uint32_t k0, uint32_t k1, uint32_t& x0, uint32_t& x1) {
    const uint32_t ks0 = k0, ks1 = k1, ks2 = k0 ^ k1 ^ 0x1BD11BDAu;
    const int r0[4] = {13, 15, 26, 6};
    const int r1[4] = {17, 29, 16, 24};
    x0 += ks0; x1 += ks1;
#pragma unroll
    for (int i = 0; i < 4; i++) { x0 += x1; x1 = rotl32(x1, r0[i]); x1 ^= x0; }
    x0 += ks1; x1 += ks2 + 1u;
#pragma unroll
    for (int i = 0; i < 4; i++) { x0 += x1; x1 = rotl32(x1, r1[i]); x1 ^= x0; }
    x0 += ks2; x1 += ks0 + 2u;
#pragma unroll
    for (int i = 0; i < 4; i++) { x0 += x1; x1 = rotl32(x1, r0[i]); x1 ^= x0; }
    x0 += ks0; x1 += ks1 + 3u;
#pragma unroll
    for (int i = 0; i < 4; i++) { x0 += x1; x1 = rotl32(x1, r1[i]); x1 ^= x0; }
    x0 += ks1; x1 += ks2 + 4u;
#pragma unroll
    for (int i = 0; i < 4; i++) { x0 += x1; x1 = rotl32(x1, r0[i]); x1 ^= x0; }
    x0 += ks2; x1 += ks0 + 5u;
}

// JAX partitionable threefry random_bits (bit_width=32):
//   counts = uint64 flat index; data words = (hi32(i)=0, lo32(i)=i)
//   bits = out0 ^ out1
__device__ __forceinline__ uint32_t jax_bits_partitionable(uint32_t i) {
    uint32_t x0 = 0u, x1 = i;
    threefry2x32(0u, 42u, x0, x1);          // key(42) -> (0, 42)
    return x0 ^ x1;
}

// ---------------------------------------------------------------------------
// K4: tail. per batch: policy head at t=62, gumbel argmax, selection, fuse, out
// ---------------------------------------------------------------------------
__global__ __launch_bounds__(256) void tail_kernel(const float* __restrict__ Wp1,
                                                   const float* __restrict__ bp1,
                                                   const float* __restrict__ Wp2,
                                                   const float* __restrict__ bp2,
                                                   const float* __restrict__ Wf,
                                                   const float* __restrict__ bf,
                                                   const float* __restrict__ Wo,
                                                   const float* __restrict__ bo,
                                                   float* __restrict__ out) {
    int b = blockIdx.x;
    int tid = threadIdx.x;
    __shared__ float obs[HID];
    __shared__ float a1[64];
    __shared__ float lgt[10];
    __shared__ float cat[2 * HID];
    __shared__ float fused[HID];
    __shared__ int s_act;

    const float* rnn_b = g_rnn + (long)b * T_SZ * HID;
    if (tid < HID) {
        float v = rnn_b[63 * HID + tid];
        obs[tid] = v;
        cat[tid] = v;
    }
    __syncthreads();

    if (tid < 64) {
        float s = bp1[tid];
#pragma unroll
        for (int k = 0; k < HID; k++) s += Wp1[tid * HID + k] * obs[k];
        a1[tid] = tanhf(s);
    }
    __syncthreads();

    if (tid < 10) {
        float s = bp2[tid];
#pragma unroll
        for (int k = 0; k < 64; k++) s += Wp2[tid * 64 + k] * a1[k];
        // gumbel noise: flat index over (B,63,10), position (b, 62, tid)
        uint32_t i = (uint32_t)(b * 630 + 620 + tid);
        uint32_t bits = jax_bits_partitionable(i);
        float u = __uint_as_float((bits >> 9) | 0x3f800000u) - 1.0f;
        u = fmaxf(u, 1.1754943508222875e-38f);
        float gmb = -logf(-logf(u));
        lgt[tid] = s + gmb;
    }
    __syncthreads();

    if (tid == 0) {
        int best = 0;
        float bv = lgt[0];
#pragma unroll
        for (int a = 1; a < 10; a++) {
            if (lgt[a] > bv) { bv = lgt[a]; best = a; }
        }
        s_act = best;   // t=63: history_start=53, len=10, clip keeps [0,9]
    }
    __syncthreads();

    if (tid < HID) cat[HID + tid] = rnn_b[(53 + s_act) * HID + tid];
    __syncthreads();

    if (tid < HID) {
        float s = bf[tid];
#pragma unroll
        for (int k = 0; k < 2 * HID; k++) s += Wf[tid * 2 * HID + k] * cat[k];
        fused[tid] = fmaxf(s, 0.f);
    }
    __syncthreads();

    if (tid < 200) {
        float s = bo[tid];
#pragma unroll
        for (int k = 0; k < HID; k++) s += Wo[tid * HID + k] * fused[k];
        out[b * 200 + tid] = s;
    }
}

// ---------------------------------------------------------------------------
extern "C" void kernel_launch(void* const* d_in, const int* in_sizes, int n_in,
                              void* d_out, int out_size) {
    // input dispatch by element count (equal-size pairs keep dict order)
    const void* p_cond = 0; const void* p_proc = 0;
    const void* p_embc = 0; const void* p_embp = 0;
    const void* p_wih = 0;  const void* p_whh = 0;
    const void* p_bih = 0;  const void* p_bhh = 0;
    const void* p_wp1 = 0;  const void* p_bp1 = 0;
    const void* p_wp2 = 0;  const void* p_bp2 = 0;
    const void* p_wf = 0;   const void* p_bf = 0;
    const void* p_wo = 0;   const void* p_bo = 0;

    for (int i = 0; i < n_in; i++) {
        int s = in_sizes[i];
        const void* p = d_in[i];
        switch (s) {
            case 196608: if (!p_cond) p_cond = p; else p_proc = p; break;   // (128,64,24)
            case 640128: if (!p_embc) p_embc = p; else p_embp = p; break;   // (5001,128)
            case  98304: p_wih = p; break;                                  // (384,256)
            case  49152: p_whh = p; break;                                  // (384,128)
            case    384: if (!p_bih) p_bih = p; else p_bhh = p; break;
            case   8192: p_wp1 = p; break;                                  // (64,128)
            case     64: p_bp1 = p; break;
            case    640: p_wp2 = p; break;                                  // (10,64)
            case     10: p_bp2 = p; break;
            case  32768: p_wf = p; break;                                   // (128,256)
            case    128: p_bf = p; break;
            case  25600: p_wo = p; break;                                   // (200,128)
            case    200: p_bo = p; break;
            default: break;
        }
    }

    float* out = (float*)d_out;

    embed_kernel<<<2048, 256>>>((const int*)p_cond, (const int*)p_proc,
                                (const float*)p_embc, (const float*)p_embp);

    dim3 g2(B_SZ * T_SZ / BM, G3 / BN);
    xproj_gemm<<<g2, 256>>>((const float*)p_wih, (const float*)p_bih);

    gru_kernel<<<B_SZ, G3>>>((const float*)p_whh, (const float*)p_bhh);

    tail_kernel<<<B_SZ, 256>>>((const float*)p_wp1, (const float*)p_bp1,
                               (const float*)p_wp2, (const float*)p_bp2,
                               (const float*)p_wf,  (const float*)p_bf,
                               (const float*)p_wo,  (const float*)p_bo, out);
}

// round 6
// speedup vs baseline: 1.1815x; 1.1815x over previous
#include <cuda_runtime.h>
#include <cstdint>

// ---------------------------------------------------------------------------
// ClinicalRLModel: embed-sum -> x@W_ih^T -> GRU(64 steps) -> policy logits at
// obs t=62 (rnn t=63) -> threefry gumbel argmax -> select rnn[53+act] ->
// fused=relu([rnn63,sel]@Wf^T+bf) -> out = fused@Wo^T+bo
// RNG: JAX partitionable threefry, 32-bit bits = out0 ^ out1, counter=(0, i).
// ---------------------------------------------------------------------------

#define B_SZ 128
#define T_SZ 64
#define C_SZ 24
#define EMB 128
#define HID 128
#define G3 384           // 3*HID
#define K2E 256          // 2*EMB

// scratch (device globals: no allocation allowed)
__device__ float g_x[B_SZ * T_SZ * K2E];      // (8192, 256)
__device__ float g_xproj[B_SZ * T_SZ * G3];   // (8192, 384)
__device__ float g_rnn[B_SZ * T_SZ * HID];    // (128, 64, 128)

// ---------------------------------------------------------------------------
// K1: embedding gather + sum over C, writes x = [e1 | e2]
// ---------------------------------------------------------------------------
__global__ void embed_kernel(const int* __restrict__ cond,
                             const int* __restrict__ proc,
                             const float* __restrict__ emb_c,
                             const float* __restrict__ emb_p) {
    int gw   = (blockIdx.x * blockDim.x + threadIdx.x) >> 5;
    int lane = threadIdx.x & 31;
    if (gw >= B_SZ * T_SZ * 2) return;
    int table = gw & 1;
    int bt    = gw >> 1;

    const int*   idx = (table ? proc : cond) + bt * C_SZ;
    const float* tab = table ? emb_p : emb_c;

    float4 acc = make_float4(0.f, 0.f, 0.f, 0.f);
#pragma unroll
    for (int j = 0; j < C_SZ; j++) {
        int r = __ldg(&idx[j]);
        float4 v = __ldg(((const float4*)(tab + (long)r * EMB)) + lane);
        acc.x += v.x; acc.y += v.y; acc.z += v.z; acc.w += v.w;
    }
    ((float4*)(g_x + (long)bt * K2E + table * EMB))[lane] = acc;
}

// ---------------------------------------------------------------------------
// K2: x_proj = x @ W_ih^T + b_ih   (M=8192, N=384, K=256), fp32 SIMT tiled
// ---------------------------------------------------------------------------
#define BM 64
#define BN 64
#define BKK 16
__global__ __launch_bounds__(256) void xproj_gemm(const float* __restrict__ Wih,
                                                  const float* __restrict__ bih) {
    __shared__ float As[BKK][BM + 4];
    __shared__ float Bs[BKK][BN + 4];
    int bm = blockIdx.x * BM;
    int bn = blockIdx.y * BN;
    int tid = threadIdx.x;
    int tx = tid & 15, ty = tid >> 4;

    int lrow = tid >> 2;          // 0..63
    int lcol = (tid & 3) * 4;     // 0,4,8,12

    float acc[4][4] = {};
    for (int k0 = 0; k0 < K2E; k0 += BKK) {
        float4 av = *(const float4*)(g_x + (long)(bm + lrow) * K2E + k0 + lcol);
        float4 bv = *(const float4*)(Wih + (long)(bn + lrow) * K2E + k0 + lcol);
        As[lcol + 0][lrow] = av.x; As[lcol + 1][lrow] = av.y;
        As[lcol + 2][lrow] = av.z; As[lcol + 3][lrow] = av.w;
        Bs[lcol + 0][lrow] = bv.x; Bs[lcol + 1][lrow] = bv.y;
        Bs[lcol + 2][lrow] = bv.z; Bs[lcol + 3][lrow] = bv.w;
        __syncthreads();
#pragma unroll
        for (int kk = 0; kk < BKK; kk++) {
            float a[4], b[4];
#pragma unroll
            for (int i = 0; i < 4; i++) a[i] = As[kk][ty * 4 + i];
#pragma unroll
            for (int i = 0; i < 4; i++) b[i] = Bs[kk][tx * 4 + i];
#pragma unroll
            for (int i = 0; i < 4; i++)
#pragma unroll
                for (int j = 0; j < 4; j++) acc[i][j] += a[i] * b[j];
        }
        __syncthreads();
    }
#pragma unroll
    for (int i = 0; i < 4; i++) {
        int m = bm + ty * 4 + i;
#pragma unroll
        for (int j = 0; j < 4; j++) {
            int n = bn + tx * 4 + j;
            g_xproj[(long)m * G3 + n] = acc[i][j] + bih[n];
        }
    }
}

// ---------------------------------------------------------------------------
// K3: GRU. one block per batch row; 384 threads; W_hh register-resident
// ---------------------------------------------------------------------------
__global__ __launch_bounds__(G3) void gru_kernel(const float* __restrict__ Whh,
                                                 const float* __restrict__ bhh) {
    int b = blockIdx.x;
    int g = threadIdx.x;      // 0..383
    __shared__ float h_sh[HID];
    __shared__ float srz[2 * HID];
    __shared__ float sxn[HID];
    __shared__ float shn[HID];

    float w[HID];
#pragma unroll
    for (int k = 0; k < HID; k += 4) {
        float4 v = *(const float4*)(Whh + (long)g * HID + k);
        w[k] = v.x; w[k + 1] = v.y; w[k + 2] = v.z; w[k + 3] = v.w;
    }
    float bb = bhh[g];
    if (g < HID) h_sh[g] = 0.f;
    __syncthreads();

    const float* xp_base = g_xproj + (long)b * T_SZ * G3;
    float* rnn_base = g_rnn + (long)b * T_SZ * HID;

    for (int t = 0; t < T_SZ; t++) {
        float xp = xp_base[t * G3 + g];
        float acc = bb;
#pragma unroll
        for (int k = 0; k < HID; k++) acc += w[k] * h_sh[k];
        if (g < 2 * HID) {
            srz[g] = xp + acc;
        } else {
            sxn[g - 2 * HID] = xp;
            shn[g - 2 * HID] = acc;
        }
        __syncthreads();
        if (g < HID) {
            float r = 1.f / (1.f + expf(-srz[g]));
            float z = 1.f / (1.f + expf(-srz[HID + g]));
            float n = tanhf(sxn[g] + r * shn[g]);
            float hn = (1.f - z) * n + z * h_sh[g];
            h_sh[g] = hn;
            rnn_base[t * HID + g] = hn;
        }
        __syncthreads();
    }
}

// ---------------------------------------------------------------------------
// threefry2x32, JAX-exact (key injections + rotation schedule)
// ---------------------------------------------------------------------------
__device__ __forceinline__ uint32_t rotl32(uint32_t v, int d) {
    return (v << d) | (v >> (32 - d));
}
__device__ void threefry2x32(uint32_t k0, uint32_t k1, uint32_t& x0, uint32_t& x1) {
    const uint32_t ks0 = k0, ks1 = k1, ks2 = k0 ^ k1 ^ 0x1BD11BDAu;
    const int r0[4] = {13, 15, 26, 6};
    const int r1[4] = {17, 29, 16, 24};
    x0 += ks0; x1 += ks1;
#pragma unroll
    for (int i = 0; i < 4; i++) { x0 += x1; x1 = rotl32(x1, r0[i]); x1 ^= x0; }
    x0 += ks1; x1 += ks2 + 1u;
#pragma unroll
    for (int i = 0; i < 4; i++) { x0 += x1; x1 = rotl32(x1, r1[i]); x1 ^= x0; }
    x0 += ks2; x1 += ks0 + 2u;
#pragma unroll
    for (int i = 0; i < 4; i++) { x0 += x1; x1 = rotl32(x1, r0[i]); x1 ^= x0; }
    x0 += ks0; x1 += ks1 + 3u;
#pragma unroll
    for (int i = 0; i < 4; i++) { x0 += x1; x1 = rotl32(x1, r1[i]); x1 ^= x0; }
    x0 += ks1; x1 += ks2 + 4u;
#pragma unroll
    for (int i = 0; i < 4; i++) { x0 += x1; x1 = rotl32(x1, r0[i]); x1 ^= x0; }
    x0 += ks2; x1 += ks0 + 5u;
}

// JAX partitionable threefry random_bits (bit_width=32): bits = out0 ^ out1
__device__ __forceinline__ uint32_t jax_bits_partitionable(uint32_t i) {
    uint32_t x0 = 0u, x1 = i;
    threefry2x32(0u, 42u, x0, x1);          // key(42) -> (0, 42)
    return x0 ^ x1;
}

// ---------------------------------------------------------------------------
// K4 v2: warp-parallel coalesced matvecs.
// one block per batch row, 256 threads = 8 warps.
// ---------------------------------------------------------------------------
__device__ __forceinline__ float warp_reduce_sum(float v) {
    v += __shfl_down_sync(0xffffffffu, v, 16);
    v += __shfl_down_sync(0xffffffffu, v, 8);
    v += __shfl_down_sync(0xffffffffu, v, 4);
    v += __shfl_down_sync(0xffffffffu, v, 2);
    v += __shfl_down_sync(0xffffffffu, v, 1);
    return v;
}

__global__ __launch_bounds__(256) void tail_kernel(const float* __restrict__ Wp1,
                                                   const float* __restrict__ bp1,
                                                   const float* __restrict__ Wp2,
                                                   const float* __restrict__ bp2,
                                                   const float* __restrict__ Wf,
                                                   const float* __restrict__ bf,
                                                   const float* __restrict__ Wo,
                                                   const float* __restrict__ bo,
                                                   float* __restrict__ out) {
    int b = blockIdx.x;
    int tid = threadIdx.x;
    int w = tid >> 5;
    int l = tid & 31;

    __shared__ float cat[2 * HID];   // [rnn63 | selected]
    __shared__ float a1[64];
    __shared__ float lgt[10];
    __shared__ float fused[HID];
    __shared__ int s_act;

    const float* rnn_b = g_rnn + (long)b * T_SZ * HID;
    if (tid < HID) cat[tid] = rnn_b[63 * HID + tid];
    __syncthreads();

    // a1[j] = tanh(Wp1[j,:] . obs + bp1[j]) : 64 outputs, 8 per warp, coalesced
    {
        int j = w * 8;
#pragma unroll
        for (int jj = 0; jj < 8; jj++, j++) {
            const float* row = Wp1 + j * HID;
            float s = row[l] * cat[l]
                    + row[l + 32] * cat[l + 32]
                    + row[l + 64] * cat[l + 64]
                    + row[l + 96] * cat[l + 96];
            s = warp_reduce_sum(s);
            if (l == 0) a1[j] = tanhf(s + bp1[j]);
        }
    }
    __syncthreads();

    // logits: 10 outputs on warp 0 (K=64: 2 loads/lane)
    if (w == 0) {
#pragma unroll
        for (int j = 0; j < 10; j++) {
            const float* row = Wp2 + j * 64;
            float s = row[l] * a1[l] + row[l + 32] * a1[l + 32];
            s = warp_reduce_sum(s);
            if (l == 0) lgt[j] = s + bp2[j];
        }
    }
    __syncthreads();

    // gumbel noise + argmax (first-max-wins)
    if (tid < 10) {
        uint32_t i = (uint32_t)(b * 630 + 620 + tid);
        uint32_t bits = jax_bits_partitionable(i);
        float u = __uint_as_float((bits >> 9) | 0x3f800000u) - 1.0f;
        u = fmaxf(u, 1.1754943508222875e-38f);
        lgt[tid] += -logf(-logf(u));
    }
    __syncthreads();
    if (tid == 0) {
        int best = 0;
        float bv = lgt[0];
#pragma unroll
        for (int a = 1; a < 10; a++)
            if (lgt[a] > bv) { bv = lgt[a]; best = a; }
        s_act = best;   // t=63: history window [53,63), clip keeps [0,9]
    }
    __syncthreads();

    if (tid < HID) cat[HID + tid] = rnn_b[(53 + s_act) * HID + tid];
    __syncthreads();

    // fused[j] = relu(Wf[j,:] . cat + bf[j]) : 128 outputs, 16 per warp, K=256
    {
        int j = w * 16;
#pragma unroll
        for (int jj = 0; jj < 16; jj++, j++) {
            const float* row = Wf + j * 2 * HID;
            float s = 0.f;
#pragma unroll
            for (int q = 0; q < 8; q++) s += row[l + 32 * q] * cat[l + 32 * q];
            s = warp_reduce_sum(s);
            if (l == 0) fused[j] = fmaxf(s + bf[j], 0.f);
        }
    }
    __syncthreads();

    // out[j] = Wo[j,:] . fused + bo[j] : 200 outputs, 25 per warp, K=128
    {
        int j = w * 25;
#pragma unroll
        for (int jj = 0; jj < 25; jj++, j++) {
            const float* row = Wo + j * HID;
            float s = row[l] * fused[l]
                    + row[l + 32] * fused[l + 32]
                    + row[l + 64] * fused[l + 64]
                    + row[l + 96] * fused[l + 96];
            s = warp_reduce_sum(s);
            if (l == 0) out[b * 200 + j] = s + bo[j];
        }
    }
}

// ---------------------------------------------------------------------------
extern "C" void kernel_launch(void* const* d_in, const int* in_sizes, int n_in,
                              void* d_out, int out_size) {
    // input dispatch by element count (equal-size pairs keep dict order)
    const void* p_cond = 0; const void* p_proc = 0;
    const void* p_embc = 0; const void* p_embp = 0;
    const void* p_wih = 0;  const void* p_whh = 0;
    const void* p_bih = 0;  const void* p_bhh = 0;
    const void* p_wp1 = 0;  const void* p_bp1 = 0;
    const void* p_wp2 = 0;  const void* p_bp2 = 0;
    const void* p_wf = 0;   const void* p_bf = 0;
    const void* p_wo = 0;   const void* p_bo = 0;

    for (int i = 0; i < n_in; i++) {
        int s = in_sizes[i];
        const void* p = d_in[i];
        switch (s) {
            case 196608: if (!p_cond) p_cond = p; else p_proc = p; break;   // (128,64,24)
            case 640128: if (!p_embc) p_embc = p; else p_embp = p; break;   // (5001,128)
            case  98304: p_wih = p; break;                                  // (384,256)
            case  49152: p_whh = p; break;                                  // (384,128)
            case    384: if (!p_bih) p_bih = p; else p_bhh = p; break;
            case   8192: p_wp1 = p; break;                                  // (64,128)
            case     64: p_bp1 = p; break;
            case    640: p_wp2 = p; break;                                  // (10,64)
            case     10: p_bp2 = p; break;
            case  32768: p_wf = p; break;                                   // (128,256)
            case    128: p_bf = p; break;
            case  25600: p_wo = p; break;                                   // (200,128)
            case    200: p_bo = p; break;
            default: break;
        }
    }

    float* out = (float*)d_out;

    embed_kernel<<<2048, 256>>>((const int*)p_cond, (const int*)p_proc,
                                (const float*)p_embc, (const float*)p_embp);

    dim3 g2(B_SZ * T_SZ / BM, G3 / BN);
    xproj_gemm<<<g2, 256>>>((const float*)p_wih, (const float*)p_bih);

    gru_kernel<<<B_SZ, G3>>>((const float*)p_whh, (const float*)p_bhh);

    tail_kernel<<<B_SZ, 256>>>((const float*)p_wp1, (const float*)p_bp1,
                               (const float*)p_wp2, (const float*)p_bp2,
                               (const float*)p_wf,  (const float*)p_bf,
                               (const float*)p_wo,  (const float*)p_bo, out);
}